// round 1
// baseline (speedup 1.0000x reference)
#include <cuda_runtime.h>

#define NN 100000
#define EI 800000
#define EE 400000
#define HH 128
#define GG 256
#define TM 32
#define N_LAYERS 4

// ---------------- scratch (static __device__, no runtime alloc) ----------------
__device__ float g_h [NN*HH];
__device__ float g_vp[NN*HH];
__device__ float g_vl[NN*HH];
__device__ float g_Ai[NN*HH];
__device__ float g_Ae[NN*HH];
__device__ float g_wint[EE];
__device__ int   g_degi[NN];
__device__ int   g_dege[NN];
__device__ float g_sif[NN];   // 1/(deg_i+1)
__device__ float g_bfi[NN];   // deg_i/(deg_i+1)
__device__ float g_sef[NN];   // log(deg_e+1)
__device__ float g_bfe[NN];   // deg_e*log(deg_e+1)
__device__ float g_pool[GG*HH];

__device__ __forceinline__ float silu_f(float x){ return x / (1.f + __expf(-x)); }

// ---------------- init / degree kernels ----------------
__global__ void k_zero_small(){
    int i = blockIdx.x*blockDim.x + threadIdx.x;
    if (i < NN){ g_degi[i]=0; g_dege[i]=0; }
    if (i < GG*HH) g_pool[i] = 0.f;
}

__global__ void k_node_init(const float* __restrict__ x,
                            const float* __restrict__ W,
                            const float* __restrict__ b){
    __shared__ float Ws[35*HH];
    __shared__ float xs[16*35];
    int t = threadIdx.x;           // 128
    int n0 = blockIdx.x*16;
    for (int i = t; i < 35*HH; i += 128) Ws[i] = W[i];
    for (int i = t; i < 16*35; i += 128){
        int node = i/35, k = i - node*35;
        xs[i] = x[(n0+node)*35 + k];
    }
    __syncthreads();
    float bb = b[t];
    for (int node = 0; node < 16; node++){
        float acc = bb;
        #pragma unroll
        for (int k = 0; k < 35; k++) acc += xs[node*35+k]*Ws[k*HH+t];
        g_h[(n0+node)*HH + t] = silu_f(acc);
    }
    // zero v_p, v_l, A_i, A_e rows for these nodes
    float4 z = make_float4(0.f,0.f,0.f,0.f);
    int base4 = n0*32;  // float4 index
    for (int i = t; i < 16*32; i += 128){
        ((float4*)g_vp)[base4+i] = z;
        ((float4*)g_vl)[base4+i] = z;
        ((float4*)g_Ai)[base4+i] = z;
        ((float4*)g_Ae)[base4+i] = z;
    }
}

__global__ void k_count_intra(const int* __restrict__ ei){
    int e = blockIdx.x*blockDim.x + threadIdx.x;
    if (e >= EI) return;
    atomicAdd(&g_degi[ei[EI+e]], 1);
}

__global__ void k_count_inter(const int* __restrict__ ee, const float* __restrict__ pos){
    int e = blockIdx.x*blockDim.x + threadIdx.x;
    if (e >= EE) return;
    int s = ee[e], d = ee[EE+e];
    float dx = pos[s*3+0]-pos[d*3+0];
    float dy = pos[s*3+1]-pos[d*3+1];
    float dz = pos[s*3+2]-pos[d*3+2];
    g_wint[e] = __expf(-(dx*dx+dy*dy+dz*dz));
    atomicAdd(&g_dege[d], 1);
}

__global__ void k_factors(){
    int i = blockIdx.x*blockDim.x + threadIdx.x;
    if (i >= NN) return;
    float di = (float)g_degi[i];
    float de = (float)g_dege[i];
    float inv = 1.f/(di+1.f);
    g_sif[i] = inv;
    g_bfi[i] = di*inv;
    float L = logf(de+1.f);
    g_sef[i] = L;
    g_bfe[i] = de*L;
}

// ---------------- edge scatter: A[dst] += w[e]*h[src] (warp per edge) ----------------
__global__ void k_scatter_intra(const int* __restrict__ eidx, const float* __restrict__ w){
    int t = blockIdx.x*blockDim.x + threadIdx.x;
    int e = t >> 5;
    if (e >= EI) return;
    int lane = t & 31;
    int s = __ldg(&eidx[e]);
    int d = __ldg(&eidx[EI+e]);
    float ww = __ldg(&w[e]);
    float4 hv = *(const float4*)&g_h[s*HH + lane*4];
    float4 v = make_float4(hv.x*ww, hv.y*ww, hv.z*ww, hv.w*ww);
    atomicAdd((float4*)&g_Ai[d*HH + lane*4], v);
}

__global__ void k_scatter_inter(const int* __restrict__ eidx){
    int t = blockIdx.x*blockDim.x + threadIdx.x;
    int e = t >> 5;
    if (e >= EE) return;
    int lane = t & 31;
    int s = __ldg(&eidx[e]);
    int d = __ldg(&eidx[EE+e]);
    float ww = g_wint[e];
    float4 hv = *(const float4*)&g_h[s*HH + lane*4];
    float4 v = make_float4(hv.x*ww, hv.y*ww, hv.z*ww, hv.w*ww);
    atomicAdd((float4*)&g_Ae[d*HH + lane*4], v);
}

// ---------------- fused per-layer: dual GEMM + norm + bias + SiLU + state update ----------------
// m_i = (A_i @ W_i) * sif + b_i * bfi ; v_p = silu(m_i + v_p)
// m_e = (A_e @ W_e) * sef + b_e * bfe ; v_l = silu(m_e + v_l)
// h  += v_p + v_l ; A_i = A_e = 0 (ready for next layer)
#define SMEM_LAYER (size_t)((128*256 + 4*TM*HH) * sizeof(float))   // 196608

__global__ void __launch_bounds__(256,1) k_layer(
        const float* __restrict__ Wi, const float* __restrict__ We,
        const float* __restrict__ bi, const float* __restrict__ be)
{
    extern __shared__ float sm[];
    float* ws  = sm;                 // [128][256] : cols 0..127 = W_i, 128..255 = W_e
    float* asi = ws  + 128*256;      // [TM][128]
    float* ase = asi + TM*HH;
    float* svp = ase + TM*HH;
    float* svl = svp + TM*HH;
    int tid = threadIdx.x;

    // Load both weight matrices once per block (persistent blocks)
    for (int i = tid; i < 8192; i += 256){
        int k = i >> 6;
        int c = (i & 63) * 4;
        float4 v = (c < 128) ? *(const float4*)&Wi[k*128 + c]
                             : *(const float4*)&We[k*128 + (c-128)];
        *(float4*)&ws[k*256 + c] = v;
    }

    int cg = tid & 63, ng = tid >> 6;
    int ccol = cg*4;                       // 0..255 (combined column)
    bool isIntra = (ccol < 128);
    int colb = isIntra ? ccol : (ccol - 128);
    float4 bvec = isIntra ? *(const float4*)&bi[colb] : *(const float4*)&be[colb];
    const float* ab0 = (isIntra ? asi : ase) + ng*8*HH;
    float* svs = isIntra ? svp : svl;
    float* gv  = isIntra ? g_vp : g_vl;

    for (int tile = blockIdx.x; tile < NN/TM; tile += gridDim.x){
        int n0 = tile*TM;

        // load A tiles (also serves as barrier: prior tile's sv-readers are done)
        for (int i = tid; i < 1024; i += 256){
            int off4 = n0*32 + i;
            ((float4*)asi)[i] = ((const float4*)g_Ai)[off4];
            ((float4*)ase)[i] = ((const float4*)g_Ae)[off4];
        }
        __syncthreads();

        // dual GEMM: 32 nodes x 256 combined cols, K=128, packed f32x2 FMA
        unsigned long long acc[8][2];
        #pragma unroll
        for (int r = 0; r < 8; r++){ acc[r][0] = 0ull; acc[r][1] = 0ull; }

        #pragma unroll 2
        for (int k0 = 0; k0 < 128; k0 += 4){
            float4 a4[8];
            #pragma unroll
            for (int r = 0; r < 8; r++)
                a4[r] = *(const float4*)&ab0[r*HH + k0];
            #pragma unroll
            for (int kk = 0; kk < 4; kk++){
                ulonglong2 w2 = *(const ulonglong2*)&ws[(k0+kk)*256 + ccol];
                #pragma unroll
                for (int r = 0; r < 8; r++){
                    float a = (kk==0)?a4[r].x:(kk==1)?a4[r].y:(kk==2)?a4[r].z:a4[r].w;
                    unsigned long long aa;
                    asm("mov.b64 %0, {%1, %1};" : "=l"(aa) : "f"(a));
                    asm("fma.rn.f32x2 %0, %1, %2, %0;" : "+l"(acc[r][0]) : "l"(aa), "l"(w2.x));
                    asm("fma.rn.f32x2 %0, %1, %2, %0;" : "+l"(acc[r][1]) : "l"(aa), "l"(w2.y));
                }
            }
        }

        // epilogue: scale + bias + SiLU, write v_p / v_l
        #pragma unroll
        for (int r = 0; r < 8; r++){
            int nl = ng*8 + r;
            int n  = n0 + nl;
            float sc = isIntra ? g_sif[n] : g_sef[n];
            float bf = isIntra ? g_bfi[n] : g_bfe[n];
            float2 p0 = *(float2*)&acc[r][0];
            float2 p1 = *(float2*)&acc[r][1];
            float4 vold = *(const float4*)&gv[n*HH + colb];
            float v0 = silu_f(p0.x*sc + bvec.x*bf + vold.x);
            float v1 = silu_f(p0.y*sc + bvec.y*bf + vold.y);
            float v2 = silu_f(p1.x*sc + bvec.z*bf + vold.z);
            float v3 = silu_f(p1.y*sc + bvec.w*bf + vold.w);
            float4 vnew = make_float4(v0,v1,v2,v3);
            *(float4*)&gv[n*HH + colb] = vnew;
            *(float4*)&svs[nl*HH + colb] = vnew;
        }
        __syncthreads();

        // h += v_p + v_l ; zero A for next layer
        float4 z = make_float4(0.f,0.f,0.f,0.f);
        for (int i = tid; i < 1024; i += 256){
            int off4 = n0*32 + i;
            float4 hv = ((float4*)g_h)[off4];
            float4 p  = ((float4*)svp)[i];
            float4 q  = ((float4*)svl)[i];
            hv.x += p.x+q.x; hv.y += p.y+q.y; hv.z += p.z+q.z; hv.w += p.w+q.w;
            ((float4*)g_h)[off4] = hv;
            ((float4*)g_Ai)[off4] = z;
            ((float4*)g_Ae)[off4] = z;
        }
    }
}

// ---------------- pooling over sorted batch ----------------
__global__ void k_pool(const int* __restrict__ batch){
    int c = threadIdx.x;              // 128 cols
    int n0 = blockIdx.x*512;
    if (n0 >= NN) return;
    int nend = min(n0+512, NN);
    int cur = batch[n0];
    float acc = 0.f;
    for (int n = n0; n < nend; n++){
        int b = batch[n];
        if (b != cur){
            atomicAdd(&g_pool[cur*HH+c], acc);
            acc = 0.f; cur = b;
        }
        acc += g_h[n*HH+c];
    }
    atomicAdd(&g_pool[cur*HH+c], acc);
}

// ---------------- FC head: 3x (linear+leaky+BN) + output linear ----------------
__global__ void k_fc(const float* __restrict__ fcW, const float* __restrict__ fcb,
                     const float* __restrict__ gam, const float* __restrict__ bet,
                     const float* __restrict__ oW,  const float* __restrict__ ob,
                     float* __restrict__ out){
    int g = blockIdx.x, c = threadIdx.x;  // 128 threads
    __shared__ float s[HH];
    __shared__ float red[HH];
    s[c] = g_pool[g*HH + c];
    __syncthreads();
    const float bns = rsqrtf(1.f + 1e-5f);
    for (int j = 0; j < 3; j++){
        const float* W = fcW + j*HH*HH;
        float acc = fcb[j*HH+c];
        #pragma unroll 8
        for (int k = 0; k < HH; k++) acc += s[k]*W[k*HH+c];
        acc = acc > 0.f ? acc : 0.01f*acc;
        acc = acc*bns*gam[j*HH+c] + bet[j*HH+c];
        __syncthreads();
        s[c] = acc;
        __syncthreads();
    }
    red[c] = s[c]*oW[c];
    __syncthreads();
    for (int o = 64; o > 0; o >>= 1){
        if (c < o) red[c] += red[c+o];
        __syncthreads();
    }
    if (c == 0) out[g] = red[0] + ob[0];
}

// ---------------- host ----------------
extern "C" void kernel_launch(void* const* d_in, const int* in_sizes, int n_in,
                              void* d_out, int out_size){
    const float* x    = (const float*)d_in[0];
    const int*   ei   = (const int*)  d_in[1];
    const int*   ee   = (const int*)  d_in[2];
    const float* pos  = (const float*)d_in[3];
    const float* ea   = (const float*)d_in[4];
    const int*   batch= (const int*)  d_in[5];
    const float* lnW  = (const float*)d_in[6];
    const float* lnb  = (const float*)d_in[7];
    const float* Wi   = (const float*)d_in[8];
    const float* bi   = (const float*)d_in[9];
    const float* We   = (const float*)d_in[10];
    const float* be   = (const float*)d_in[11];
    const float* fcW  = (const float*)d_in[12];
    const float* fcb  = (const float*)d_in[13];
    const float* gam  = (const float*)d_in[14];
    const float* bet  = (const float*)d_in[15];
    const float* oW   = (const float*)d_in[16];
    const float* ob   = (const float*)d_in[17];
    float* out = (float*)d_out;

    cudaFuncSetAttribute(k_layer, cudaFuncAttributeMaxDynamicSharedMemorySize, (int)SMEM_LAYER);

    k_zero_small<<<(NN+255)/256, 256>>>();
    k_node_init<<<NN/16, 128>>>(x, lnW, lnb);
    k_count_intra<<<(EI+255)/256, 256>>>(ei);
    k_count_inter<<<(EE+255)/256, 256>>>(ee, pos);
    k_factors<<<(NN+255)/256, 256>>>();

    for (int l = 0; l < N_LAYERS; l++){
        k_scatter_intra<<<EI*32/256, 256>>>(ei, ea);
        k_scatter_inter<<<EE*32/256, 256>>>(ee);
        k_layer<<<148, 256, SMEM_LAYER>>>(Wi + l*HH*HH, We + l*HH*HH,
                                          bi + l*HH,    be + l*HH);
    }

    k_pool<<<(NN+511)/512, 128>>>(batch);
    k_fc<<<GG, 128>>>(fcW, fcb, gam, bet, oW, ob, out);
}

// round 2
// speedup vs baseline: 1.2565x; 1.2565x over previous
#include <cuda_runtime.h>

#define NN 100000
#define NP 100032          // padded to 1563*64
#define EI 800000
#define EE 400000
#define HH 128
#define GG 256
#define N_LAYERS 4
#define NTILES 1563        // ceil(NN/64)

// ---------------- scratch (static __device__, no runtime alloc) ----------------
__device__ float g_h [NP*HH];
__device__ float g_vp[NP*HH];
__device__ float g_vl[NP*HH];
__device__ float g_Ai[NP*HH];
__device__ float g_Ae[NP*HH];
__device__ float g_wint[EE];
__device__ int   g_degi[NN];
__device__ int   g_dege[NN];
__device__ float g_sif[NP];   // 1/(deg_i+1)
__device__ float g_bfi[NP];   // deg_i/(deg_i+1)
__device__ float g_sef[NP];   // log(deg_e+1)
__device__ float g_bfe[NP];   // deg_e*log(deg_e+1)
__device__ int   g_offi[NN+1];
__device__ int   g_offe[NN+1];
__device__ int   g_curi[NN];
__device__ int   g_cure[NN];
__device__ int   g_srci[EI];
__device__ float g_wi[EI];
__device__ int   g_srce[EE];
__device__ float g_we[EE];
__device__ int   g_parti[128];
__device__ int   g_parte[128];
__device__ float g_pool[GG*HH];

__device__ __forceinline__ float silu_f(float x){ return x / (1.f + __expf(-x)); }
__device__ __forceinline__ unsigned long long dup2(float a){
    unsigned long long r; asm("mov.b64 %0, {%1, %1};" : "=l"(r) : "f"(a)); return r;
}
__device__ __forceinline__ void ffma2(unsigned long long& acc, unsigned long long a, unsigned long long b){
    asm("fma.rn.f32x2 %0, %1, %2, %0;" : "+l"(acc) : "l"(a), "l"(b));
}

// ---------------- 0: node init (lin_node + SiLU) + zero vp/vl + zero degrees ----------------
__global__ void k_node_init(const float* __restrict__ x,
                            const float* __restrict__ W,
                            const float* __restrict__ b){
    __shared__ float Ws[35*HH];
    __shared__ float xs[16*35];
    int t = threadIdx.x;           // 128
    int n0 = blockIdx.x*16;
    for (int i = t; i < 35*HH; i += 128) Ws[i] = W[i];
    for (int i = t; i < 16*35; i += 128){
        int node = i/35, k = i - node*35;
        xs[i] = x[(n0+node)*35 + k];
    }
    if (t < 16){ g_degi[n0+t] = 0; g_dege[n0+t] = 0; }
    __syncthreads();
    float bb = b[t];
    for (int node = 0; node < 16; node++){
        float acc = bb;
        #pragma unroll
        for (int k = 0; k < 35; k++) acc += xs[node*35+k]*Ws[k*HH+t];
        g_h[(n0+node)*HH + t] = silu_f(acc);
    }
    float4 z = make_float4(0.f,0.f,0.f,0.f);
    int base4 = n0*32;
    for (int i = t; i < 16*32; i += 128){
        ((float4*)g_vp)[base4+i] = z;
        ((float4*)g_vl)[base4+i] = z;
    }
}

// ---------------- 1: degree counts + inter geometric weight ----------------
__global__ void k_count(const int* __restrict__ ei, const int* __restrict__ ee,
                        const float* __restrict__ pos){
    int t = blockIdx.x*blockDim.x + threadIdx.x;
    if (t < EI){
        atomicAdd(&g_degi[ei[EI+t]], 1);
    } else if (t < EI+EE){
        int e = t - EI;
        int s = ee[e], d = ee[EE+e];
        float dx = pos[s*3+0]-pos[d*3+0];
        float dy = pos[s*3+1]-pos[d*3+1];
        float dz = pos[s*3+2]-pos[d*3+2];
        g_wint[e] = __expf(-(dx*dx+dy*dy+dz*dz));
        atomicAdd(&g_dege[d], 1);
    }
}

// ---------------- 2: per-chunk inclusive scan (1024 nodes/block) ----------------
__global__ void k_scan1(){
    __shared__ int s[1024];
    int b0 = blockIdx.x*1024;
    for (int pass = 0; pass < 2; pass++){
        const int* deg = pass ? g_dege : g_degi;
        int* off  = pass ? g_offe : g_offi;
        int* part = pass ? g_parte : g_parti;
        for (int i = threadIdx.x; i < 1024; i += 256){
            int n = b0 + i; s[i] = (n < NN) ? deg[n] : 0;
        }
        __syncthreads();
        for (int d = 1; d < 1024; d <<= 1){
            int t[4];
            #pragma unroll
            for (int j = 0; j < 4; j++){
                int i = threadIdx.x + j*256;
                t[j] = (i >= d) ? s[i-d] : 0;
            }
            __syncthreads();
            #pragma unroll
            for (int j = 0; j < 4; j++){
                int i = threadIdx.x + j*256;
                s[i] += t[j];
            }
            __syncthreads();
        }
        for (int i = threadIdx.x; i < 1024; i += 256){
            int n = b0 + i; if (n < NN) off[n+1] = s[i];
        }
        if (threadIdx.x == 0) part[blockIdx.x] = s[1023];
        __syncthreads();
    }
}

// ---------------- 3: add chunk bases + cursors + degree factors ----------------
__global__ void k_scan2(){
    __shared__ int basei_s, basee_s;
    int b = blockIdx.x;
    if (threadIdx.x == 0){
        int bi = 0, be = 0;
        for (int j = 0; j < b; j++){ bi += g_parti[j]; be += g_parte[j]; }
        basei_s = bi; basee_s = be;
    }
    __syncthreads();
    int basei = basei_s, basee = basee_s;
    int b0 = b*1024;
    for (int i = threadIdx.x; i < 1024; i += 256){
        int n = b0 + i;
        if (n >= NN) continue;
        int di = g_degi[n], de = g_dege[n];
        int oi = g_offi[n+1] + basei;
        int oe = g_offe[n+1] + basee;
        g_offi[n+1] = oi;
        g_offe[n+1] = oe;
        g_curi[n] = oi - di;
        g_cure[n] = oe - de;
        if (n == 0){ g_offi[0] = 0; g_offe[0] = 0; }
        float fdi = (float)di, fde = (float)de;
        float inv = 1.f/(fdi+1.f);
        g_sif[n] = inv;
        g_bfi[n] = fdi*inv;
        float L = logf(fde+1.f);
        g_sef[n] = L;
        g_bfe[n] = fde*L;
    }
}

// ---------------- 4: fill CSR (src + weight, grouped by dst) ----------------
__global__ void k_fill(const int* __restrict__ ei, const float* __restrict__ ea,
                       const int* __restrict__ ee){
    int t = blockIdx.x*blockDim.x + threadIdx.x;
    if (t < EI){
        int s = ei[t], d = ei[EI+t];
        int p = atomicAdd(&g_curi[d], 1);
        g_srci[p] = s; g_wi[p] = ea[t];
    } else if (t < EI+EE){
        int e = t - EI;
        int s = ee[e], d = ee[EE+e];
        int p = atomicAdd(&g_cure[d], 1);
        g_srce[p] = s; g_we[p] = g_wint[e];
    }
}

// ---------------- per layer: gather (warp per dst node), scale folded ----------------
__global__ void __launch_bounds__(256) k_gather(){
    int gw = (blockIdx.x*256 + threadIdx.x) >> 5;
    if (gw >= NN) return;
    int lane = threadIdx.x & 31;
    int c4 = lane*4;

    // intra
    {
        int a0 = g_offi[gw], a1 = g_offi[gw+1];
        float4 acc = make_float4(0.f,0.f,0.f,0.f);
        for (int j = a0; j < a1; j++){
            int s   = __ldg(&g_srci[j]);
            float w = __ldg(&g_wi[j]);
            float4 hv = *(const float4*)&g_h[s*HH + c4];
            acc.x += w*hv.x; acc.y += w*hv.y; acc.z += w*hv.z; acc.w += w*hv.w;
        }
        float sc = g_sif[gw];
        *(float4*)&g_Ai[gw*HH + c4] = make_float4(acc.x*sc, acc.y*sc, acc.z*sc, acc.w*sc);
    }
    // inter
    {
        int a0 = g_offe[gw], a1 = g_offe[gw+1];
        float4 acc = make_float4(0.f,0.f,0.f,0.f);
        for (int j = a0; j < a1; j++){
            int s   = __ldg(&g_srce[j]);
            float w = __ldg(&g_we[j]);
            float4 hv = *(const float4*)&g_h[s*HH + c4];
            acc.x += w*hv.x; acc.y += w*hv.y; acc.z += w*hv.z; acc.w += w*hv.w;
        }
        float sc = g_sef[gw];
        *(float4*)&g_Ae[gw*HH + c4] = make_float4(acc.x*sc, acc.y*sc, acc.z*sc, acc.w*sc);
    }
}

// ---------------- per layer: dual GEMM + bias + SiLU + state update ----------------
// m_i = A_i' @ W_i + b_i*bfi ; v_p = silu(m_i + v_p)
// m_e = A_e' @ W_e + b_e*bfe ; v_l = silu(m_e + v_l)
// h += v_p + v_l
#define AST 132                       // padded row stride for A / sv smem
#define SMEM_LAYER ((128*256 + 2*64*AST)*sizeof(float))   // 198656 B

__global__ void __launch_bounds__(256,1) k_layer(
        const float* __restrict__ Wi, const float* __restrict__ We,
        const float* __restrict__ bi, const float* __restrict__ be)
{
    extern __shared__ float sm[];
    float* ws  = sm;                 // [128][256]: cols 0..127 Wi, 128..255 We
    float* asi = ws  + 128*256;      // [64][AST] A_i tile, reused as sv_p
    float* ase = asi + 64*AST;       // [64][AST] A_e tile, reused as sv_l
    int tid = threadIdx.x;
    int cg = tid & 31, rg = tid >> 5;
    int c4 = cg*4;

    for (int i = tid; i < 8192; i += 256){
        int k = i >> 6;
        int c = (i & 63)*4;
        float4 v = (c < 128) ? *(const float4*)&Wi[k*128 + c]
                             : *(const float4*)&We[k*128 + (c-128)];
        *(float4*)&ws[k*256 + c] = v;
    }
    float4 bvi = *(const float4*)&bi[c4];
    float4 bve = *(const float4*)&be[c4];

    for (int tile = blockIdx.x; tile < NTILES; tile += gridDim.x){
        int n0 = tile*64;

        // load A tiles into smem (coalesced)
        for (int i = tid; i < 2048; i += 256){
            int row = i >> 5, kc = (i & 31)*4;
            int goff = (n0+row)*HH + kc;
            *(float4*)&asi[row*AST + kc] = *(const float4*)&g_Ai[goff];
            *(float4*)&ase[row*AST + kc] = *(const float4*)&g_Ae[goff];
        }
        __syncthreads();

        unsigned long long acci[8][2], acce[8][2];
        #pragma unroll
        for (int r = 0; r < 8; r++){ acci[r][0]=0ull; acci[r][1]=0ull; acce[r][0]=0ull; acce[r][1]=0ull; }

        const float* arow_i = asi + rg*8*AST;
        const float* arow_e = ase + rg*8*AST;

        // GEMM 1: intra
        #pragma unroll 2
        for (int k0 = 0; k0 < 128; k0 += 4){
            float4 a4[8];
            #pragma unroll
            for (int r = 0; r < 8; r++) a4[r] = *(const float4*)&arow_i[r*AST + k0];
            #pragma unroll
            for (int kk = 0; kk < 4; kk++){
                ulonglong2 w2 = *(const ulonglong2*)&ws[(k0+kk)*256 + c4];
                #pragma unroll
                for (int r = 0; r < 8; r++){
                    float a = (kk==0)?a4[r].x:(kk==1)?a4[r].y:(kk==2)?a4[r].z:a4[r].w;
                    unsigned long long aa = dup2(a);
                    ffma2(acci[r][0], aa, w2.x);
                    ffma2(acci[r][1], aa, w2.y);
                }
            }
        }
        // GEMM 2: inter
        #pragma unroll 2
        for (int k0 = 0; k0 < 128; k0 += 4){
            float4 a4[8];
            #pragma unroll
            for (int r = 0; r < 8; r++) a4[r] = *(const float4*)&arow_e[r*AST + k0];
            #pragma unroll
            for (int kk = 0; kk < 4; kk++){
                ulonglong2 w2 = *(const ulonglong2*)&ws[(k0+kk)*256 + 128 + c4];
                #pragma unroll
                for (int r = 0; r < 8; r++){
                    float a = (kk==0)?a4[r].x:(kk==1)?a4[r].y:(kk==2)?a4[r].z:a4[r].w;
                    unsigned long long aa = dup2(a);
                    ffma2(acce[r][0], aa, w2.x);
                    ffma2(acce[r][1], aa, w2.y);
                }
            }
        }

        // epilogue (each warp owns rows rg*8..rg*8+7, so reusing asi/ase is race-free)
        #pragma unroll
        for (int r = 0; r < 8; r++){
            int nl = rg*8 + r;
            int n  = n0 + nl;
            float bf  = g_bfi[n];
            float bfe_ = g_bfe[n];
            float2 p0 = *(float2*)&acci[r][0];
            float2 p1 = *(float2*)&acci[r][1];
            float4 vo = *(const float4*)&g_vp[n*HH + c4];
            float4 v;
            v.x = silu_f(p0.x + bvi.x*bf + vo.x);
            v.y = silu_f(p0.y + bvi.y*bf + vo.y);
            v.z = silu_f(p1.x + bvi.z*bf + vo.z);
            v.w = silu_f(p1.y + bvi.w*bf + vo.w);
            *(float4*)&g_vp[n*HH + c4] = v;
            *(float4*)&asi[nl*AST + c4] = v;

            float2 q0 = *(float2*)&acce[r][0];
            float2 q1 = *(float2*)&acce[r][1];
            float4 uo = *(const float4*)&g_vl[n*HH + c4];
            float4 u;
            u.x = silu_f(q0.x + bve.x*bfe_ + uo.x);
            u.y = silu_f(q0.y + bve.y*bfe_ + uo.y);
            u.z = silu_f(q1.x + bve.z*bfe_ + uo.z);
            u.w = silu_f(q1.y + bve.w*bfe_ + uo.w);
            *(float4*)&g_vl[n*HH + c4] = u;
            *(float4*)&ase[nl*AST + c4] = u;
        }
        __syncthreads();

        // h += v_p + v_l
        for (int i = tid; i < 2048; i += 256){
            int row = i >> 5, kc = (i & 31)*4;
            int goff = (n0+row)*HH + kc;
            float4 hv = *(const float4*)&g_h[goff];
            float4 p  = *(const float4*)&asi[row*AST + kc];
            float4 q  = *(const float4*)&ase[row*AST + kc];
            hv.x += p.x+q.x; hv.y += p.y+q.y; hv.z += p.z+q.z; hv.w += p.w+q.w;
            *(float4*)&g_h[goff] = hv;
        }
        __syncthreads();
    }
}

// ---------------- pooling ----------------
__global__ void k_zero_pool(){
    int i = blockIdx.x*blockDim.x + threadIdx.x;
    if (i < GG*HH) g_pool[i] = 0.f;
}

__global__ void k_pool(const int* __restrict__ batch){
    int c = threadIdx.x;              // 128 cols
    int n0 = blockIdx.x*512;
    if (n0 >= NN) return;
    int nend = min(n0+512, NN);
    int cur = batch[n0];
    float acc = 0.f;
    for (int n = n0; n < nend; n++){
        int b = batch[n];
        if (b != cur){
            atomicAdd(&g_pool[cur*HH+c], acc);
            acc = 0.f; cur = b;
        }
        acc += g_h[n*HH+c];
    }
    atomicAdd(&g_pool[cur*HH+c], acc);
}

// ---------------- FC head ----------------
__global__ void k_fc(const float* __restrict__ fcW, const float* __restrict__ fcb,
                     const float* __restrict__ gam, const float* __restrict__ bet,
                     const float* __restrict__ oW,  const float* __restrict__ ob,
                     float* __restrict__ out){
    int g = blockIdx.x, c = threadIdx.x;  // 128 threads
    __shared__ float s[HH];
    __shared__ float red[HH];
    s[c] = g_pool[g*HH + c];
    __syncthreads();
    const float bns = rsqrtf(1.f + 1e-5f);
    for (int j = 0; j < 3; j++){
        const float* W = fcW + j*HH*HH;
        float acc = fcb[j*HH+c];
        #pragma unroll 8
        for (int k = 0; k < HH; k++) acc += s[k]*W[k*HH+c];
        acc = acc > 0.f ? acc : 0.01f*acc;
        acc = acc*bns*gam[j*HH+c] + bet[j*HH+c];
        __syncthreads();
        s[c] = acc;
        __syncthreads();
    }
    red[c] = s[c]*oW[c];
    __syncthreads();
    for (int o = 64; o > 0; o >>= 1){
        if (c < o) red[c] += red[c+o];
        __syncthreads();
    }
    if (c == 0) out[g] = red[0] + ob[0];
}

// ---------------- host ----------------
extern "C" void kernel_launch(void* const* d_in, const int* in_sizes, int n_in,
                              void* d_out, int out_size){
    const float* x    = (const float*)d_in[0];
    const int*   ei   = (const int*)  d_in[1];
    const int*   ee   = (const int*)  d_in[2];
    const float* pos  = (const float*)d_in[3];
    const float* ea   = (const float*)d_in[4];
    const int*   batch= (const int*)  d_in[5];
    const float* lnW  = (const float*)d_in[6];
    const float* lnb  = (const float*)d_in[7];
    const float* Wi   = (const float*)d_in[8];
    const float* bi   = (const float*)d_in[9];
    const float* We   = (const float*)d_in[10];
    const float* be   = (const float*)d_in[11];
    const float* fcW  = (const float*)d_in[12];
    const float* fcb  = (const float*)d_in[13];
    const float* gam  = (const float*)d_in[14];
    const float* bet  = (const float*)d_in[15];
    const float* oW   = (const float*)d_in[16];
    const float* ob   = (const float*)d_in[17];
    float* out = (float*)d_out;

    cudaFuncSetAttribute(k_layer, cudaFuncAttributeMaxDynamicSharedMemorySize, (int)SMEM_LAYER);

    k_node_init<<<NN/16, 128>>>(x, lnW, lnb);                 // 0
    k_count<<<(EI+EE+255)/256, 256>>>(ei, ee, pos);           // 1
    k_scan1<<<98, 256>>>();                                   // 2
    k_scan2<<<98, 256>>>();                                   // 3
    k_fill<<<(EI+EE+255)/256, 256>>>(ei, ea, ee);             // 4

    for (int l = 0; l < N_LAYERS; l++){
        k_gather<<<(NN*32+255)/256, 256>>>();                 // 5,7,9,11
        k_layer<<<148, 256, SMEM_LAYER>>>(Wi + l*HH*HH, We + l*HH*HH,
                                          bi + l*HH,    be + l*HH);  // 6,8,10,12
    }

    k_zero_pool<<<(GG*HH+255)/256, 256>>>();                  // 13
    k_pool<<<(NN+511)/512, 128>>>(batch);                     // 14
    k_fc<<<GG, 128>>>(fcW, fcb, gam, bet, oW, ob, out);       // 15
}